// round 14
// baseline (speedup 1.0000x reference)
#include <cuda_runtime.h>
#include <cuda_fp16.h>
#include <math.h>
#include <stdint.h>

// ---------------- problem dims ----------------
#define B2   2
#define S48  110592
#define S24  13824
#define S12  1728
#define EE   768
#define NH   12
#define HD   64
#define NTOK (B2*S12)     // 3456
#define KK2  1536
#define NPATCH (B2*S24)   // 27648
#define KPAIRS 864        // S12/2

// ---------------- scratch ----------------
__device__ float g_patchs[NPATCH*48];
__device__ float g_patchx[NPATCH*48];
__device__ float g_h1b   [NPATCH*192];
__device__ float g_q     [NTOK*EE];
__device__ float g_k     [NTOK*EE];
__device__ float g_v     [NTOK*EE];
__device__ float g_Wt    [192*48];
__device__ float g_S     [(size_t)B2*NH*S12*S12];   // fp32 scores
__device__ float g_att   [NTOK*EE];
__device__ float g_deb   [NTOK*KK2];
// fp16 split operands
__device__ __half g_h1bh[NTOK*KK2];
__device__ __half g_h1bl[NTOK*KK2];
__device__ __half g_qh  [NTOK*EE];
__device__ __half g_ql  [NTOK*EE];
__device__ __half g_atth[NTOK*EE];
__device__ __half g_attl[NTOK*EE];
__device__ __half g_sh  [(size_t)B2*NH*S12*S12];    // softmax out hi
__device__ __half g_sl  [(size_t)B2*NH*S12*S12];    // softmax out lo
// packed vertical-pair (half2 as uint32) B operands
__device__ uint32_t g_w2ph[768*768];     // conv2 W: [768 kpairs][768]
__device__ uint32_t g_w2pl[768*768];
__device__ uint32_t g_wdph[384*1536];    // debed W: [384 kpairs][1536]
__device__ uint32_t g_wdpl[384*1536];
__device__ uint32_t g_ktph[24*32*S12];   // K^T packed: [(z,dpair)][j]
__device__ uint32_t g_ktpl[24*32*S12];
__device__ uint32_t g_vph [B2*KPAIRS*EE]; // V packed: [b][kpair][c]
__device__ uint32_t g_vpl [B2*KPAIRS*EE];

// ---------------- helpers ----------------
__device__ __forceinline__ float blk_sum(float v, float* sh) {
    int lane = threadIdx.x & 31;
#pragma unroll
    for (int o = 16; o; o >>= 1) v += __shfl_xor_sync(0xffffffffu, v, o);
    __syncthreads();
    if (lane == 0) sh[threadIdx.x >> 5] = v;
    __syncthreads();
    int nw = blockDim.x >> 5;
    v = (lane < nw) ? sh[lane] : 0.f;
#pragma unroll
    for (int o = 16; o; o >>= 1) v += __shfl_xor_sync(0xffffffffu, v, o);
    return v;
}
__device__ __forceinline__ float blk_max(float v, float* sh) {
    int lane = threadIdx.x & 31;
#pragma unroll
    for (int o = 16; o; o >>= 1) v = fmaxf(v, __shfl_xor_sync(0xffffffffu, v, o));
    __syncthreads();
    if (lane == 0) sh[threadIdx.x >> 5] = v;
    __syncthreads();
    int nw = blockDim.x >> 5;
    v = (lane < nw) ? sh[lane] : -3.4e38f;
#pragma unroll
    for (int o = 16; o; o >>= 1) v = fmaxf(v, __shfl_xor_sync(0xffffffffu, v, o));
    return v;
}
__device__ __forceinline__ void rope_trig(float f, float& cs, float& sn) {
    float n = rintf(f * 0.15915494309189535f);
    float r = fmaf(-n, 6.28125f, f);
    r = fmaf(-n, 1.9353071795864769e-3f, r);
    cs = cosf(r);
    sn = sinf(r);
}
__device__ __forceinline__ void hsplit(float x, __half& h, __half& l) {
    h = __float2half_rn(x);
    l = __float2half_rn(x - __half2float(h));
}
__device__ __forceinline__ uint32_t h2u(__half a, __half b) {
    __half2 t = __halves2half2(a, b);
    return *(uint32_t*)&t;
}
__device__ __forceinline__ void mma_f16(float* c, const uint32_t* a, const uint32_t* b) {
    asm volatile(
        "mma.sync.aligned.m16n8k16.row.col.f32.f16.f16.f32 "
        "{%0,%1,%2,%3}, {%4,%5,%6,%7}, {%8,%9}, {%0,%1,%2,%3};\n"
        : "+f"(c[0]), "+f"(c[1]), "+f"(c[2]), "+f"(c[3])
        : "r"(a[0]), "r"(a[1]), "r"(a[2]), "r"(a[3]), "r"(b[0]), "r"(b[1]));
}

// ---------------- fused LN6 + patch gather ----------------
__global__ void k_patch(const float* __restrict__ in, const float* __restrict__ w,
                        const float* __restrict__ bb, float* __restrict__ out) {
    int id = blockIdx.x * blockDim.x + threadIdx.x;
    if (id >= NPATCH * 8) return;
    int kpq = id & 7;
    int p = id >> 3;
    int bn = p / S24, pos = p - bn * S24;
    int h = pos / 576, w24 = (pos / 24) % 24, d = pos % 24;
    int k = kpq >> 2, pp = (kpq >> 1) & 1, qq = kpq & 1;
    size_t sp = ((size_t)(2 * h + k) * 48 + 2 * w24 + pp) * 48 + 2 * d + qq;
    const float* base = in + (size_t)bn * 6 * S48 + sp;
    float v[6], u = 0.f;
#pragma unroll
    for (int c = 0; c < 6; c++) { v[c] = base[(size_t)c * S48]; u += v[c]; }
    u *= (1.f / 6.f);
    float s = 0.f;
#pragma unroll
    for (int c = 0; c < 6; c++) { float dd = v[c] - u; s += dd * dd; }
    s *= (1.f / 6.f);
    float r = rsqrtf(s + 1e-6f);
    int token = bn * S12 + (h >> 1) * 144 + (w24 >> 1) * 12 + (d >> 1);
    int par = (h & 1) * 4 + (w24 & 1) * 2 + (d & 1);
    float* ob = out + ((size_t)token * 8 + par) * 48 + kpq;
#pragma unroll
    for (int c = 0; c < 6; c++) ob[c * 8] = (v[c] - u) * r * w[c] + bb[c];
}

// ---------------- small SGEMM (conv1): 64x64 ----------------
__global__ void k_gemm64(const float* __restrict__ A, const float* __restrict__ B,
                         float* __restrict__ C, int K, int lda, int ldb, int ldc) {
    __shared__ float As[16][64];
    __shared__ float Bs[16][64];
    int tid = threadIdx.x;
    int tx = tid & 15, ty = tid >> 4;
    int n0 = blockIdx.y * 64, m0 = blockIdx.x * 64;
    int lr = tid >> 2, lc = (tid & 3) * 4;
    int br = tid >> 4, bc = (tid & 15) * 4;
    const float* Ap = A + (size_t)(n0 + lr) * lda + lc;
    const float* Bp = B + (size_t)br * ldb + m0 + bc;
    float acc[4][4] = {};
    for (int k0 = 0; k0 < K; k0 += 16) {
        float4 a  = *(const float4*)(Ap + k0);
        float4 bv = *(const float4*)(Bp + (size_t)k0 * ldb);
        __syncthreads();
        As[lc + 0][lr] = a.x; As[lc + 1][lr] = a.y; As[lc + 2][lr] = a.z; As[lc + 3][lr] = a.w;
        *(float4*)&Bs[br][bc] = bv;
        __syncthreads();
#pragma unroll
        for (int kk = 0; kk < 16; kk++) {
            float4 av = *(const float4*)&As[kk][ty * 4];
            float4 bw = *(const float4*)&Bs[kk][tx * 4];
            float aa[4] = {av.x, av.y, av.z, av.w};
            float bbv[4] = {bw.x, bw.y, bw.z, bw.w};
#pragma unroll
            for (int i = 0; i < 4; i++)
#pragma unroll
                for (int j = 0; j < 4; j++) acc[i][j] += aa[i] * bbv[j];
        }
    }
#pragma unroll
    for (int i = 0; i < 4; i++) {
        float4 o = make_float4(acc[i][0], acc[i][1], acc[i][2], acc[i][3]);
        *(float4*)&C[(size_t)(n0 + ty * 4 + i) * ldc + m0 + tx * 4] = o;
    }
}

// ---------------- dense fp16x3 MMA GEMM (pre-split): tile 64x128 ----------------
#define DAS 12
#define DBS 136
__global__ __launch_bounds__(256, 2)
void k_mma16(const __half* __restrict__ Ah, const __half* __restrict__ Al,
             const uint32_t* __restrict__ Bph, const uint32_t* __restrict__ Bpl,
             float* __restrict__ C, int K, int lda, int ldb, int ldc) {
    __shared__ uint32_t sAh[64 * DAS], sAl[64 * DAS];
    __shared__ uint32_t sBh[8 * DBS], sBl[8 * DBS];
    int tid = threadIdx.x, warp = tid >> 5, lane = tid & 31;
    int n0 = blockIdx.y * 64, m0 = blockIdx.x * 128;
    int wm = (warp >> 2) * 32, wn = (warp & 3) * 32;
    int arow = tid >> 2, aseg = tid & 3;
    int brow = tid >> 5, bc4 = (tid & 31) * 4;
    float acc[2][4][4] = {};

    for (int k0 = 0; k0 < K; k0 += 16) {
        __syncthreads();
        uint2 va = *(const uint2*)&Ah[(size_t)(n0 + arow) * lda + k0 + aseg * 4];
        uint2 vl = *(const uint2*)&Al[(size_t)(n0 + arow) * lda + k0 + aseg * 4];
        sAh[arow * DAS + aseg * 2] = va.x; sAh[arow * DAS + aseg * 2 + 1] = va.y;
        sAl[arow * DAS + aseg * 2] = vl.x; sAl[arow * DAS + aseg * 2 + 1] = vl.y;
        uint4 wh = *(const uint4*)&Bph[(size_t)(k0 / 2 + brow) * ldb + m0 + bc4];
        uint4 wl = *(const uint4*)&Bpl[(size_t)(k0 / 2 + brow) * ldb + m0 + bc4];
        *(uint4*)&sBh[brow * DBS + bc4] = wh;
        *(uint4*)&sBl[brow * DBS + bc4] = wl;
        __syncthreads();

        uint32_t a_h[2][4], a_l[2][4];
        int r0 = wm + (lane >> 2), kq = lane & 3;
#pragma unroll
        for (int ma = 0; ma < 2; ma++) {
            int r = r0 + ma * 16;
            a_h[ma][0] = sAh[r * DAS + kq];       a_h[ma][1] = sAh[(r + 8) * DAS + kq];
            a_h[ma][2] = sAh[r * DAS + kq + 4];   a_h[ma][3] = sAh[(r + 8) * DAS + kq + 4];
            a_l[ma][0] = sAl[r * DAS + kq];       a_l[ma][1] = sAl[(r + 8) * DAS + kq];
            a_l[ma][2] = sAl[r * DAS + kq + 4];   a_l[ma][3] = sAl[(r + 8) * DAS + kq + 4];
        }
        uint32_t b_h[4][2], b_l[4][2];
#pragma unroll
        for (int na = 0; na < 4; na++) {
            int c = wn + na * 8 + (lane >> 2);
            b_h[na][0] = sBh[kq * DBS + c]; b_h[na][1] = sBh[(kq + 4) * DBS + c];
            b_l[na][0] = sBl[kq * DBS + c]; b_l[na][1] = sBl[(kq + 4) * DBS + c];
        }
#pragma unroll
        for (int ma = 0; ma < 2; ma++)
#pragma unroll
            for (int na = 0; na < 4; na++) {
                mma_f16(acc[ma][na], a_h[ma], b_h[na]);
                mma_f16(acc[ma][na], a_l[ma], b_h[na]);
                mma_f16(acc[ma][na], a_h[ma], b_l[na]);
            }
    }
#pragma unroll
    for (int ma = 0; ma < 2; ma++) {
        int row = n0 + wm + ma * 16 + (lane >> 2);
#pragma unroll
        for (int na = 0; na < 4; na++) {
            int col = m0 + wn + na * 8 + (lane & 3) * 2;
            C[(size_t)row * ldc + col]           = acc[ma][na][0];
            C[(size_t)row * ldc + col + 1]       = acc[ma][na][1];
            C[(size_t)(row + 8) * ldc + col]     = acc[ma][na][2];
            C[(size_t)(row + 8) * ldc + col + 1] = acc[ma][na][3];
        }
    }
}

// ---------------- scores fp16x3 MMA: tile 64x64, K=64, 128 thr ----------------
#define QAS 36
#define KBS 72
__global__ __launch_bounds__(128)
void k_scores16(const __half* __restrict__ Qh, const __half* __restrict__ Ql,
                const uint32_t* __restrict__ Kth, const uint32_t* __restrict__ Ktl,
                float* __restrict__ S) {
    __shared__ uint32_t sAh[64 * QAS], sAl[64 * QAS];
    __shared__ uint32_t sBh[32 * KBS], sBl[32 * KBS];
    int tid = threadIdx.x, warp = tid >> 5, lane = tid & 31;
    int z = blockIdx.z, b = z / NH, h = z - b * NH;
    int i0 = blockIdx.y * 64, j0 = blockIdx.x * 64;
    const __half* qbh = Qh + (size_t)(b * S12) * EE + h * HD;
    const __half* qbl = Ql + (size_t)(b * S12) * EE + h * HD;
    size_t kbase = (size_t)z * 32 * S12;

    for (int t = tid; t < 64 * 16; t += 128) {
        int row = t >> 4, seg = t & 15;
        uint2 va = *(const uint2*)&qbh[(size_t)(i0 + row) * EE + seg * 4];
        uint2 vl = *(const uint2*)&qbl[(size_t)(i0 + row) * EE + seg * 4];
        sAh[row * QAS + seg * 2] = va.x; sAh[row * QAS + seg * 2 + 1] = va.y;
        sAl[row * QAS + seg * 2] = vl.x; sAl[row * QAS + seg * 2 + 1] = vl.y;
    }
    for (int t = tid; t < 32 * 16; t += 128) {
        int row = t >> 4, c4 = (t & 15) * 4;
        *(uint4*)&sBh[row * KBS + c4] = *(const uint4*)&Kth[kbase + (size_t)row * S12 + j0 + c4];
        *(uint4*)&sBl[row * KBS + c4] = *(const uint4*)&Ktl[kbase + (size_t)row * S12 + j0 + c4];
    }
    __syncthreads();

    float acc[2][4][4] = {};
    int wm = (warp >> 1) * 32, wn = (warp & 1) * 32;
    int r0 = wm + (lane >> 2), kq = lane & 3;
#pragma unroll
    for (int kk = 0; kk < 4; kk++) {
        int kb = kk * 8;
        uint32_t a_h[2][4], a_l[2][4];
#pragma unroll
        for (int ma = 0; ma < 2; ma++) {
            int r = r0 + ma * 16;
            a_h[ma][0] = sAh[r * QAS + kb + kq];       a_h[ma][1] = sAh[(r + 8) * QAS + kb + kq];
            a_h[ma][2] = sAh[r * QAS + kb + kq + 4];   a_h[ma][3] = sAh[(r + 8) * QAS + kb + kq + 4];
            a_l[ma][0] = sAl[r * QAS + kb + kq];       a_l[ma][1] = sAl[(r + 8) * QAS + kb + kq];
            a_l[ma][2] = sAl[r * QAS + kb + kq + 4];   a_l[ma][3] = sAl[(r + 8) * QAS + kb + kq + 4];
        }
        uint32_t b_h[4][2], b_l[4][2];
#pragma unroll
        for (int na = 0; na < 4; na++) {
            int c = wn + na * 8 + (lane >> 2);
            b_h[na][0] = sBh[(kb + kq) * KBS + c]; b_h[na][1] = sBh[(kb + kq + 4) * KBS + c];
            b_l[na][0] = sBl[(kb + kq) * KBS + c]; b_l[na][1] = sBl[(kb + kq + 4) * KBS + c];
        }
#pragma unroll
        for (int ma = 0; ma < 2; ma++)
#pragma unroll
            for (int na = 0; na < 4; na++) {
                mma_f16(acc[ma][na], a_h[ma], b_h[na]);
                mma_f16(acc[ma][na], a_l[ma], b_h[na]);
                mma_f16(acc[ma][na], a_h[ma], b_l[na]);
            }
    }
    float* Sz = S + (size_t)z * S12 * S12;
#pragma unroll
    for (int ma = 0; ma < 2; ma++) {
        int row = i0 + wm + ma * 16 + (lane >> 2);
#pragma unroll
        for (int na = 0; na < 4; na++) {
            int col = j0 + wn + na * 8 + (lane & 3) * 2;
            Sz[(size_t)row * S12 + col]           = acc[ma][na][0];
            Sz[(size_t)row * S12 + col + 1]       = acc[ma][na][1];
            Sz[(size_t)(row + 8) * S12 + col]     = acc[ma][na][2];
            Sz[(size_t)(row + 8) * S12 + col + 1] = acc[ma][na][3];
        }
    }
}

// ---------------- PV fp16x3 MMA: tile 64x64, K=S12, 128 thr ----------------
#define PAS 12
#define PBS 72
__global__ __launch_bounds__(128)
void k_pv16(const __half* __restrict__ Sh, const __half* __restrict__ Sl,
            const uint32_t* __restrict__ Vph, const uint32_t* __restrict__ Vpl,
            float* __restrict__ O) {
    __shared__ uint32_t sAh[64 * PAS], sAl[64 * PAS];
    __shared__ uint32_t sBh[8 * PBS], sBl[8 * PBS];
    int tid = threadIdx.x, warp = tid >> 5, lane = tid & 31;
    int z = blockIdx.y, b = z / NH, h = z - b * NH;
    int i0 = blockIdx.x * 64;
    size_t sbase = (size_t)z * S12 * S12;
    size_t vbase = (size_t)b * KPAIRS * EE + h * HD;
    int wm = (warp >> 1) * 32, wn = (warp & 1) * 32;
    int arow = tid >> 1, aoff = (tid & 1) * 8;
    int brow = tid >> 4, bc4 = (tid & 15) * 4;
    float acc[2][4][4] = {};

    for (int k0 = 0; k0 < S12; k0 += 16) {
        __syncthreads();
        uint4 va = *(const uint4*)&Sh[sbase + (size_t)(i0 + arow) * S12 + k0 + aoff];
        uint4 vl = *(const uint4*)&Sl[sbase + (size_t)(i0 + arow) * S12 + k0 + aoff];
        *(uint4*)&sAh[arow * PAS + (aoff >> 1)] = va;
        *(uint4*)&sAl[arow * PAS + (aoff >> 1)] = vl;
        *(uint4*)&sBh[brow * PBS + bc4] = *(const uint4*)&Vph[vbase + (size_t)(k0 / 2 + brow) * EE + bc4];
        *(uint4*)&sBl[brow * PBS + bc4] = *(const uint4*)&Vpl[vbase + (size_t)(k0 / 2 + brow) * EE + bc4];
        __syncthreads();

        uint32_t a_h[2][4], a_l[2][4];
        int r0 = wm + (lane >> 2), kq = lane & 3;
#pragma unroll
        for (int ma = 0; ma < 2; ma++) {
            int r = r0 + ma * 16;
            a_h[ma][0] = sAh[r * PAS + kq];       a_h[ma][1] = sAh[(r + 8) * PAS + kq];
            a_h[ma][2] = sAh[r * PAS + kq + 4];   a_h[ma][3] = sAh[(r + 8) * PAS + kq + 4];
            a_l[ma][0] = sAl[r * PAS + kq];       a_l[ma][1] = sAl[(r + 8) * PAS + kq];
            a_l[ma][2] = sAl[r * PAS + kq + 4];   a_l[ma][3] = sAl[(r + 8) * PAS + kq + 4];
        }
        uint32_t b_h[4][2], b_l[4][2];
#pragma unroll
        for (int na = 0; na < 4; na++) {
            int c = wn + na * 8 + (lane >> 2);
            b_h[na][0] = sBh[kq * PBS + c]; b_h[na][1] = sBh[(kq + 4) * PBS + c];
            b_l[na][0] = sBl[kq * PBS + c]; b_l[na][1] = sBl[(kq + 4) * PBS + c];
        }
#pragma unroll
        for (int ma = 0; ma < 2; ma++)
#pragma unroll
            for (int na = 0; na < 4; na++) {
                mma_f16(acc[ma][na], a_h[ma], b_h[na]);
                mma_f16(acc[ma][na], a_l[ma], b_h[na]);
                mma_f16(acc[ma][na], a_h[ma], b_l[na]);
            }
    }
#pragma unroll
    for (int ma = 0; ma < 2; ma++) {
        int row = i0 + wm + ma * 16 + (lane >> 2);
        float* o0 = O + (size_t)(b * S12 + row) * EE + h;
        float* o1 = O + (size_t)(b * S12 + row + 8) * EE + h;
#pragma unroll
        for (int na = 0; na < 4; na++) {
            int c0 = wn + na * 8 + (lane & 3) * 2;
            o0[c0 * NH]       = acc[ma][na][0];
            o0[(c0 + 1) * NH] = acc[ma][na][1];
            o1[c0 * NH]       = acc[ma][na][2];
            o1[(c0 + 1) * NH] = acc[ma][na][3];
        }
    }
}

// ---------------- LN over 768 (+RoPE) fp32 in-place ----------------
__global__ void k_ln768(float* __restrict__ X, const float* __restrict__ w,
                        const float* __restrict__ bb, int doRope) {
    __shared__ float s[768];
    __shared__ float sh[32];
    int n = blockIdx.x, tid = threadIdx.x;
    float* row = X + (size_t)n * 768;
    float partial = 0.f;
#pragma unroll
    for (int it = 0; it < 3; it++) { int j = tid + it * 256; float v = row[j]; s[j] = v; partial += v; }
    float u = blk_sum(partial, sh) * (1.f / 768.f);
    float p2 = 0.f;
#pragma unroll
    for (int it = 0; it < 3; it++) { int j = tid + it * 256; float dd = s[j] - u; p2 += dd * dd; }
    float var = blk_sum(p2, sh) * (1.f / 768.f);
    float rinv = rsqrtf(var + 1e-6f);
#pragma unroll
    for (int it = 0; it < 3; it++) { int j = tid + it * 256; s[j] = (s[j] - u) * rinv * w[j] + bb[j]; }
    __syncthreads();
    if (doRope) {
        int l = n % S12;
#pragma unroll
        for (int it = 0; it < 3; it++) {
            int j = tid + it * 256;
            int jm = (j < 384) ? j : j - 384;
            float inv = exp2f(-(float)jm * (13.287712379549449f / 384.f));
            float f = (float)l * inv;
            float cs, sn;
            rope_trig(f, cs, sn);
            float rot = (j < 384) ? -s[j + 384] : s[j - 384];
            row[j] = s[j] * cs + rot * sn;
        }
    } else {
#pragma unroll
        for (int it = 0; it < 3; it++) { int j = tid + it * 256; row[j] = s[j]; }
    }
}

// ---------------- LN768 (no rope) -> fp16 hi/lo ----------------
__global__ void k_ln768h(const float* __restrict__ X, const float* __restrict__ w,
                         const float* __restrict__ bb, __half* __restrict__ oh,
                         __half* __restrict__ ol) {
    __shared__ float s[768];
    __shared__ float sh[32];
    int n = blockIdx.x, tid = threadIdx.x;
    const float* row = X + (size_t)n * 768;
    float partial = 0.f;
#pragma unroll
    for (int it = 0; it < 3; it++) { int j = tid + it * 256; float v = row[j]; s[j] = v; partial += v; }
    float u = blk_sum(partial, sh) * (1.f / 768.f);
    float p2 = 0.f;
#pragma unroll
    for (int it = 0; it < 3; it++) { int j = tid + it * 256; float dd = s[j] - u; p2 += dd * dd; }
    float var = blk_sum(p2, sh) * (1.f / 768.f);
    float rinv = rsqrtf(var + 1e-6f);
#pragma unroll
    for (int it = 0; it < 3; it++) {
        int j = tid + it * 256;
        float val = (s[j] - u) * rinv * w[j] + bb[j];
        __half h, l;
        hsplit(val, h, l);
        oh[(size_t)n * 768 + j] = h;
        ol[(size_t)n * 768 + j] = l;
    }
}

// ---------------- softmax -> split fp16 (scale already folded into Q!) ----------------
__global__ void k_softmax(const float* __restrict__ S, __half* __restrict__ oh,
                          __half* __restrict__ ol) {
    __shared__ float sh[32];
    int row = blockIdx.x;
    const float* r = S + (size_t)row * S12;
    int tid = threadIdx.x;
    float vals[7];
    float mx = -3.4e38f;
    for (int i = 0, j = tid; j < S12; j += 256, i++) { float v = r[j]; vals[i] = v; mx = fmaxf(mx, v); }
    mx = blk_max(mx, sh);
    float sum = 0.f;
    for (int i = 0, j = tid; j < S12; j += 256, i++) {
        float e = expf(vals[i] - mx);     // FIXED: no extra 0.125 — Q pre-scaled
        vals[i] = e; sum += e;
    }
    sum = blk_sum(sum, sh);
    float inv = 1.f / sum;
    for (int i = 0, j = tid; j < S12; j += 256, i++) {
        float val = vals[i] * inv;
        __half h, l;
        hsplit(val, h, l);
        oh[(size_t)row * S12 + j] = h;
        ol[(size_t)row * S12 + j] = l;
    }
}

// ---------------- split kernels ----------------
__global__ void k_splitQ(const float* __restrict__ in, __half* __restrict__ oh,
                         __half* __restrict__ ol, int n, float scale) {
    int i = blockIdx.x * blockDim.x + threadIdx.x;
    if (i >= n) return;
    float x = in[i] * scale;
    __half h, l;
    hsplit(x, h, l);
    oh[i] = h; ol[i] = l;
}
__global__ void k_splitW2p(const float* __restrict__ in, uint32_t* __restrict__ bh,
                           uint32_t* __restrict__ bl) {
    int idx = blockIdx.x * blockDim.x + threadIdx.x;
    if (idx >= 768 * 96 * 8) return;
    int o = idx % 768;
    int rest = idx / 768;
    int par = rest & 7, t2 = rest >> 3;
    float a = in[o * 1536 + (2 * t2) * 8 + par];
    float c = in[o * 1536 + (2 * t2 + 1) * 8 + par];
    __half ah, al, ch, cl;
    hsplit(a, ah, al); hsplit(c, ch, cl);
    size_t oi = (size_t)(par * 96 + t2) * 768 + o;
    bh[oi] = h2u(ah, ch);
    bl[oi] = h2u(al, cl);
}
__global__ void k_splitWdp(const float* __restrict__ in, uint32_t* __restrict__ bh,
                           uint32_t* __restrict__ bl) {
    int idx = blockIdx.x * blockDim.x + threadIdx.x;
    if (idx >= 384 * 1536) return;
    int m = idx % 1536;
    int i2 = idx / 1536;
    int r = m / 192, o2 = m % 192;
    float a = in[(2 * i2) * 1536 + o2 * 8 + r];
    float c = in[(2 * i2 + 1) * 1536 + o2 * 8 + r];
    __half ah, al, ch, cl;
    hsplit(a, ah, al); hsplit(c, ch, cl);
    bh[idx] = h2u(ah, ch);
    bl[idx] = h2u(al, cl);
}
__global__ void k_transKp(const float* __restrict__ Kf, uint32_t* __restrict__ oh,
                          uint32_t* __restrict__ ol) {
    __shared__ float sm[32][33];
    int z = blockIdx.z, b = z / NH, h = z - b * NH;
    int j0 = blockIdx.x * 32, d0 = blockIdx.y * 32;
    int tx = threadIdx.x, ty = threadIdx.y;
    const float* kb = Kf + (size_t)b * S12 * EE + h * HD;
#pragma unroll
    for (int jy = 0; jy < 4; jy++) {
        int j = ty * 4 + jy;
        sm[j][tx] = kb[(size_t)(j0 + j) * EE + d0 + tx];
    }
    __syncthreads();
    uint32_t* ohz = oh + (size_t)z * 32 * S12;
    uint32_t* olz = ol + (size_t)z * 32 * S12;
#pragma unroll
    for (int dy = 0; dy < 2; dy++) {
        int dp = ty * 2 + dy;
        float a = sm[tx][2 * dp], c = sm[tx][2 * dp + 1];
        __half ah, al, ch, cl;
        hsplit(a, ah, al); hsplit(c, ch, cl);
        size_t oi = (size_t)(d0 / 2 + dp) * S12 + j0 + tx;
        ohz[oi] = h2u(ah, ch);
        olz[oi] = h2u(al, cl);
    }
}
__global__ void k_packV(const float* __restrict__ V, uint32_t* __restrict__ oh,
                        uint32_t* __restrict__ ol) {
    int idx = blockIdx.x * blockDim.x + threadIdx.x;
    if (idx >= B2 * KPAIRS * EE) return;
    int c = idx % EE;
    int kp = (idx / EE) % KPAIRS;
    int b = idx / (EE * KPAIRS);
    float a = V[((size_t)b * S12 + 2 * kp) * EE + c];
    float d = V[((size_t)b * S12 + 2 * kp + 1) * EE + c];
    __half ah, al, dh, dl;
    hsplit(a, ah, al); hsplit(d, dh, dl);
    oh[idx] = h2u(ah, dh);
    ol[idx] = h2u(al, dl);
}

// ---------------- conv1 weight transpose ----------------
__global__ void k_transW1(const float* __restrict__ in, float* __restrict__ out) {
    int idx = blockIdx.x * blockDim.x + threadIdx.x;
    if (idx >= 192 * 48) return;
    int t = idx / 48, j = idx - t * 48;
    out[j * 192 + t] = in[idx];
}

// ---------------- LN192+GELU -> fp16 hi/lo ----------------
__global__ void k_ln192gelu_h(const float* __restrict__ X, const float* __restrict__ g,
                              const float* __restrict__ bb, __half* __restrict__ oh,
                              __half* __restrict__ ol) {
    __shared__ float sh[32];
    int n = blockIdx.x, t = threadIdx.x;
    const float* row = X + (size_t)n * 192;
    float v = row[t];
    float u = blk_sum(v, sh) * (1.f / 192.f);
    float dd = v - u;
    float var = blk_sum(dd * dd, sh) * (1.f / 192.f);
    float xn = dd * rsqrtf(var + 1e-6f) * g[t] + bb[t];
    float ge = xn * normcdff(xn);
    __half h, l;
    hsplit(ge, h, l);
    oh[(size_t)n * 192 + t] = h;
    ol[(size_t)n * 192 + t] = l;
}
// ---------------- LN192+GELU fp32 in place (debed) ----------------
__global__ void k_ln192gelu(float* __restrict__ X, const float* __restrict__ g,
                            const float* __restrict__ bb) {
    __shared__ float sh[32];
    int n = blockIdx.x, t = threadIdx.x;
    float* row = X + (size_t)n * 192;
    float v = row[t];
    float u = blk_sum(v, sh) * (1.f / 192.f);
    float dd = v - u;
    float var = blk_sum(dd * dd, sh) * (1.f / 192.f);
    float xn = dd * rsqrtf(var + 1e-6f) * g[t] + bb[t];
    row[t] = xn * normcdff(xn);
}

// ---------------- final convT2s2 (192->6) + bias + residual ----------------
__global__ void k_debed2(const float* __restrict__ glo, const float* __restrict__ W,
                         const float* __restrict__ bias, const float* __restrict__ res,
                         float* __restrict__ out) {
    __shared__ float row[192];
    int bid = blockIdx.x;
    int bn = bid / S24, pos = bid - bn * S24;
    int H = pos / 576, Wp = (pos / 24) % 24, D = pos % 24;
    int n1 = (H >> 1) * 144 + (Wp >> 1) * 12 + (D >> 1);
    int rr = (H & 1) * 4 + (Wp & 1) * 2 + (D & 1);
    const float* rp = glo + (size_t)(bn * S12 + n1) * KK2 + rr * 192;
    int t = threadIdx.x;
    for (int j = t; j < 192; j += 64) row[j] = rp[j];
    __syncthreads();
    if (t < 48) {
        int c = t >> 3, r2 = t & 7;
        float acc = 0.f;
#pragma unroll
        for (int o = 0; o < 192; o++) acc += row[o] * __ldg(&W[o * 48 + c * 8 + r2]);
        int Hf = 2 * H + (r2 >> 2), Wf = 2 * Wp + ((r2 >> 1) & 1), Df = 2 * D + (r2 & 1);
        size_t oi = (((size_t)(bn * 6 + c) * 48 + Hf) * 48 + Wf) * 48 + Df;
        out[oi] = acc + bias[c] + res[oi];
    }
}

// ---------------- launch ----------------
extern "C" void kernel_launch(void* const* d_in, const int* in_sizes, int n_in,
                              void* d_out, int out_size) {
    const float* x     = (const float*)d_in[0];
    const float* skip  = (const float*)d_in[1];
    const float* o_tw1 = (const float*)d_in[20];
    const float* o_g   = (const float*)d_in[21];
    const float* o_b   = (const float*)d_in[22];
    const float* o_tw2 = (const float*)d_in[23];
    const float* o_tb2 = (const float*)d_in[24];
    const float* ns_w  = (const float*)d_in[25];
    const float* ns_b  = (const float*)d_in[26];
    const float* nx_w  = (const float*)d_in[27];
    const float* nx_b  = (const float*)d_in[28];
    const float* no_w  = (const float*)d_in[29];
    const float* no_b  = (const float*)d_in[30];
    float* out = (float*)d_out;

    float *patchs, *patchx, *h1b, *q, *k, *v, *Wt, *S, *att, *deb;
    __half *h1bh, *h1bl, *qh, *ql, *atth, *attl, *shp, *slp;
    uint32_t *w2ph, *w2pl, *wdph, *wdpl, *ktph, *ktpl, *vph, *vpl;
    cudaGetSymbolAddress((void**)&patchs, g_patchs);
    cudaGetSymbolAddress((void**)&patchx, g_patchx);
    cudaGetSymbolAddress((void**)&h1b,    g_h1b);
    cudaGetSymbolAddress((void**)&q,      g_q);
    cudaGetSymbolAddress((void**)&k,      g_k);
    cudaGetSymbolAddress((void**)&v,      g_v);
    cudaGetSymbolAddress((void**)&Wt,     g_Wt);
    cudaGetSymbolAddress((void**)&S,      g_S);
    cudaGetSymbolAddress((void**)&att,    g_att);
    cudaGetSymbolAddress((void**)&deb,    g_deb);
    cudaGetSymbolAddress((void**)&h1bh,   g_h1bh);
    cudaGetSymbolAddress((void**)&h1bl,   g_h1bl);
    cudaGetSymbolAddress((void**)&qh,     g_qh);
    cudaGetSymbolAddress((void**)&ql,     g_ql);
    cudaGetSymbolAddress((void**)&atth,   g_atth);
    cudaGetSymbolAddress((void**)&attl,   g_attl);
    cudaGetSymbolAddress((void**)&shp,    g_sh);
    cudaGetSymbolAddress((void**)&slp,    g_sl);
    cudaGetSymbolAddress((void**)&w2ph,   g_w2ph);
    cudaGetSymbolAddress((void**)&w2pl,   g_w2pl);
    cudaGetSymbolAddress((void**)&wdph,   g_wdph);
    cudaGetSymbolAddress((void**)&wdpl,   g_wdpl);
    cudaGetSymbolAddress((void**)&ktph,   g_ktph);
    cudaGetSymbolAddress((void**)&ktpl,   g_ktpl);
    cudaGetSymbolAddress((void**)&vph,    g_vph);
    cudaGetSymbolAddress((void**)&vpl,    g_vpl);

    k_patch<<<(NPATCH * 8 + 255) / 256, 256>>>(skip, ns_w, ns_b, patchs);
    k_patch<<<(NPATCH * 8 + 255) / 256, 256>>>(x,    nx_w, nx_b, patchx);

    const float* stem_patch[3] = {patchs, patchx, patchx};
    float* stem_out[3] = {q, k, v};
    int rope[3] = {1, 1, 0};
    for (int si = 0; si < 3; si++) {
        int base = 2 + si * 6;
        const float* w1 = (const float*)d_in[base + 0];
        const float* g1 = (const float*)d_in[base + 1];
        const float* b1 = (const float*)d_in[base + 2];
        const float* w2 = (const float*)d_in[base + 3];
        const float* g2 = (const float*)d_in[base + 4];
        const float* b2 = (const float*)d_in[base + 5];
        k_transW1<<<(192 * 48 + 255) / 256, 256>>>(w1, Wt);
        dim3 g1g(192 / 64, NPATCH / 64);
        k_gemm64<<<g1g, 256>>>(stem_patch[si], Wt, h1b, 48, 48, 192, 192);
        k_ln192gelu_h<<<NPATCH, 192>>>(h1b, g1, b1, h1bh, h1bl);
        k_splitW2p<<<(768 * 96 * 8 + 255) / 256, 256>>>(w2, w2ph, w2pl);
        dim3 gg(EE / 128, NTOK / 64);
        k_mma16<<<gg, 256>>>(h1bh, h1bl, w2ph, w2pl, stem_out[si], KK2, KK2, EE, EE);
        k_ln768<<<NTOK, 256>>>(stem_out[si], g2, b2, rope[si]);
    }

    // attention operand prep
    k_splitQ<<<(NTOK * EE + 255) / 256, 256>>>(q, qh, ql, NTOK * EE, 0.125f);
    k_transKp<<<dim3(S12 / 32, 2, B2 * NH), dim3(32, 8)>>>(k, ktph, ktpl);
    k_packV<<<(B2 * KPAIRS * EE + 255) / 256, 256>>>(v, vph, vpl);

    k_scores16<<<dim3(27, 27, 24), 128>>>(qh, ql, ktph, ktpl, S);
    k_softmax<<<B2 * NH * S12, 256>>>(S, shp, slp);
    k_pv16<<<dim3(27, 24), 128>>>(shp, slp, vph, vpl, att);

    k_ln768h<<<NTOK, 256>>>(att, no_w, no_b, atth, attl);
    k_splitWdp<<<(384 * 1536 + 255) / 256, 256>>>(o_tw1, wdph, wdpl);
    dim3 gd(KK2 / 128, NTOK / 64);
    k_mma16<<<gd, 256>>>(atth, attl, wdph, wdpl, deb, EE, EE, KK2, KK2);
    k_ln192gelu<<<NTOK * 8, 192>>>(deb, o_g, o_b);
    k_debed2<<<B2 * S24, 64>>>(deb, o_tw2, o_tb2, skip, out);
}

// round 15
// speedup vs baseline: 1.3749x; 1.3749x over previous
#include <cuda_runtime.h>
#include <cuda_fp16.h>
#include <math.h>
#include <stdint.h>

// ---------------- problem dims ----------------
#define B2   2
#define S48  110592
#define S24  13824
#define S12  1728
#define EE   768
#define NH   12
#define HD   64
#define NTOK (B2*S12)     // 3456
#define KK2  1536
#define NPATCH (B2*S24)   // 27648

// ---------------- scratch ----------------
__device__ float g_patchs[NPATCH*48];
__device__ float g_patchx[NPATCH*48];
__device__ float g_h1b   [NPATCH*192];
__device__ float g_q     [NTOK*EE];
__device__ float g_k     [NTOK*EE];
__device__ float g_v     [NTOK*EE];
__device__ float g_Wt    [KK2*EE];
__device__ float g_S     [(size_t)B2*NH*S12*S12];
__device__ float g_att   [NTOK*EE];
__device__ float g_deb   [NTOK*KK2];
__device__ float g_Kt    [(size_t)B2*NH*HD*S12];   // per-head K^T fp32

// ---------------- helpers ----------------
__device__ __forceinline__ float blk_sum(float v, float* sh) {
    int lane = threadIdx.x & 31;
#pragma unroll
    for (int o = 16; o; o >>= 1) v += __shfl_xor_sync(0xffffffffu, v, o);
    __syncthreads();
    if (lane == 0) sh[threadIdx.x >> 5] = v;
    __syncthreads();
    int nw = blockDim.x >> 5;
    v = (lane < nw) ? sh[lane] : 0.f;
#pragma unroll
    for (int o = 16; o; o >>= 1) v += __shfl_xor_sync(0xffffffffu, v, o);
    return v;
}
__device__ __forceinline__ float blk_max(float v, float* sh) {
    int lane = threadIdx.x & 31;
#pragma unroll
    for (int o = 16; o; o >>= 1) v = fmaxf(v, __shfl_xor_sync(0xffffffffu, v, o));
    __syncthreads();
    if (lane == 0) sh[threadIdx.x >> 5] = v;
    __syncthreads();
    int nw = blockDim.x >> 5;
    v = (lane < nw) ? sh[lane] : -3.4e38f;
#pragma unroll
    for (int o = 16; o; o >>= 1) v = fmaxf(v, __shfl_xor_sync(0xffffffffu, v, o));
    return v;
}
__device__ __forceinline__ void rope_trig(float f, float& cs, float& sn) {
    float n = rintf(f * 0.15915494309189535f);
    float r = fmaf(-n, 6.28125f, f);
    r = fmaf(-n, 1.9353071795864769e-3f, r);
    cs = cosf(r);
    sn = sinf(r);
}
__device__ __forceinline__ uint32_t pack_h2(float a, float b) {
    __half2 h = __halves2half2(__float2half_rn(a), __float2half_rn(b));
    return *(uint32_t*)&h;
}
__device__ __forceinline__ void split_f16(float x, float& hi, float& lo) {
    __half h = __float2half_rn(x);
    hi = __half2float(h);
    lo = x - hi;
}
__device__ __forceinline__ void mma_f16(float* c, const uint32_t* a, const uint32_t* b) {
    asm volatile(
        "mma.sync.aligned.m16n8k16.row.col.f32.f16.f16.f32 "
        "{%0,%1,%2,%3}, {%4,%5,%6,%7}, {%8,%9}, {%0,%1,%2,%3};\n"
        : "+f"(c[0]), "+f"(c[1]), "+f"(c[2]), "+f"(c[3])
        : "r"(a[0]), "r"(a[1]), "r"(a[2]), "r"(a[3]), "r"(b[0]), "r"(b[1]));
}

// ---------------- fused LN6 + patch gather ----------------
__global__ void k_patch(const float* __restrict__ in, const float* __restrict__ w,
                        const float* __restrict__ bb, float* __restrict__ out) {
    int id = blockIdx.x * blockDim.x + threadIdx.x;
    if (id >= NPATCH * 8) return;
    int kpq = id & 7;
    int p = id >> 3;
    int bn = p / S24, pos = p - bn * S24;
    int h = pos / 576, w24 = (pos / 24) % 24, d = pos % 24;
    int k = kpq >> 2, pp = (kpq >> 1) & 1, qq = kpq & 1;
    size_t sp = ((size_t)(2 * h + k) * 48 + 2 * w24 + pp) * 48 + 2 * d + qq;
    const float* base = in + (size_t)bn * 6 * S48 + sp;
    float v[6], u = 0.f;
#pragma unroll
    for (int c = 0; c < 6; c++) { v[c] = base[(size_t)c * S48]; u += v[c]; }
    u *= (1.f / 6.f);
    float s = 0.f;
#pragma unroll
    for (int c = 0; c < 6; c++) { float dd = v[c] - u; s += dd * dd; }
    s *= (1.f / 6.f);
    float r = rsqrtf(s + 1e-6f);
    int token = bn * S12 + (h >> 1) * 144 + (w24 >> 1) * 12 + (d >> 1);
    int par = (h & 1) * 4 + (w24 & 1) * 2 + (d & 1);
    float* ob = out + ((size_t)token * 8 + par) * 48 + kpq;
#pragma unroll
    for (int c = 0; c < 6; c++) ob[c * 8] = (v[c] - u) * r * w[c] + bb[c];
}

// ---------------- small SGEMM (conv1): 64x64 ----------------
__global__ void k_gemm64(const float* __restrict__ A, const float* __restrict__ B,
                         float* __restrict__ C, int K, int lda, int ldb, int ldc) {
    __shared__ float As[16][64];
    __shared__ float Bs[16][64];
    int tid = threadIdx.x;
    int tx = tid & 15, ty = tid >> 4;
    int n0 = blockIdx.y * 64, m0 = blockIdx.x * 64;
    int lr = tid >> 2, lc = (tid & 3) * 4;
    int br = tid >> 4, bc = (tid & 15) * 4;
    const float* Ap = A + (size_t)(n0 + lr) * lda + lc;
    const float* Bp = B + (size_t)br * ldb + m0 + bc;
    float acc[4][4] = {};
    for (int k0 = 0; k0 < K; k0 += 16) {
        float4 a  = *(const float4*)(Ap + k0);
        float4 bv = *(const float4*)(Bp + (size_t)k0 * ldb);
        __syncthreads();
        As[lc + 0][lr] = a.x; As[lc + 1][lr] = a.y; As[lc + 2][lr] = a.z; As[lc + 3][lr] = a.w;
        *(float4*)&Bs[br][bc] = bv;
        __syncthreads();
#pragma unroll
        for (int kk = 0; kk < 16; kk++) {
            float4 av = *(const float4*)&As[kk][ty * 4];
            float4 bw = *(const float4*)&Bs[kk][tx * 4];
            float aa[4] = {av.x, av.y, av.z, av.w};
            float bbv[4] = {bw.x, bw.y, bw.z, bw.w};
#pragma unroll
            for (int i = 0; i < 4; i++)
#pragma unroll
                for (int j = 0; j < 4; j++) acc[i][j] += aa[i] * bbv[j];
        }
    }
#pragma unroll
    for (int i = 0; i < 4; i++) {
        float4 o = make_float4(acc[i][0], acc[i][1], acc[i][2], acc[i][3]);
        *(float4*)&C[(size_t)(n0 + ty * 4 + i) * ldc + m0 + tx * 4] = o;
    }
}

// ---------------- dense fp16x3 MMA GEMM (R11 proven): tile 64x128, in-loop split ----
#define AS_U 12
#define BS_U 136
__global__ __launch_bounds__(256, 2)
void k_mma_fp16(const float* __restrict__ A, const float* __restrict__ B,
                float* __restrict__ C, int K, int lda, int ldb, int ldc) {
    __shared__ uint32_t Ah[64 * AS_U], Al[64 * AS_U];
    __shared__ uint32_t Bh[8 * BS_U], Bl[8 * BS_U];
    int tid = threadIdx.x;
    int warp = tid >> 5, lane = tid & 31;
    int n0 = blockIdx.y * 64;
    int m0 = blockIdx.x * 128;
    int wm = (warp >> 2) * 32;
    int wn = (warp & 3) * 32;
    int ar = tid >> 2, ak4 = (tid & 3) * 4, ak2 = (tid & 3) * 2;
    int bk2 = tid >> 5, bm = (tid & 31) * 4;
    float acc[2][4][4] = {};

    for (int k0 = 0; k0 < K; k0 += 16) {
        __syncthreads();
        {
            float4 a = *(const float4*)&A[(size_t)(n0 + ar) * lda + k0 + ak4];
            float hx, lx, hy, ly, hz, lz, hw, lw;
            split_f16(a.x, hx, lx); split_f16(a.y, hy, ly);
            split_f16(a.z, hz, lz); split_f16(a.w, hw, lw);
            Ah[ar * AS_U + ak2]     = pack_h2(hx, hy);
            Ah[ar * AS_U + ak2 + 1] = pack_h2(hz, hw);
            Al[ar * AS_U + ak2]     = pack_h2(lx, ly);
            Al[ar * AS_U + ak2 + 1] = pack_h2(lz, lw);
            float4 b0 = *(const float4*)&B[(size_t)(k0 + 2 * bk2) * ldb + m0 + bm];
            float4 b1 = *(const float4*)&B[(size_t)(k0 + 2 * bk2 + 1) * ldb + m0 + bm];
            float b0v[4] = {b0.x, b0.y, b0.z, b0.w};
            float b1v[4] = {b1.x, b1.y, b1.z, b1.w};
#pragma unroll
            for (int j = 0; j < 4; j++) {
                float h0, l0, h1, l1;
                split_f16(b0v[j], h0, l0);
                split_f16(b1v[j], h1, l1);
                Bh[bk2 * BS_U + bm + j] = pack_h2(h0, h1);
                Bl[bk2 * BS_U + bm + j] = pack_h2(l0, l1);
            }
        }
        __syncthreads();

        uint32_t a_h[2][4], a_l[2][4];
        int r0 = wm + (lane >> 2);
        int kq = lane & 3;
#pragma unroll
        for (int ma = 0; ma < 2; ma++) {
            int r = r0 + ma * 16;
            a_h[ma][0] = Ah[r * AS_U + kq];
            a_h[ma][1] = Ah[(r + 8) * AS_U + kq];
            a_h[ma][2] = Ah[r * AS_U + kq + 4];
            a_h[ma][3] = Ah[(r + 8) * AS_U + kq + 4];
            a_l[ma][0] = Al[r * AS_U + kq];
            a_l[ma][1] = Al[(r + 8) * AS_U + kq];
            a_l[ma][2] = Al[r * AS_U + kq + 4];
            a_l[ma][3] = Al[(r + 8) * AS_U + kq + 4];
        }
        uint32_t b_h[4][2], b_l[4][2];
#pragma unroll
        for (int na = 0; na < 4; na++) {
            int c = wn + na * 8 + (lane >> 2);
            b_h[na][0] = Bh[kq * BS_U + c];
            b_h[na][1] = Bh[(kq + 4) * BS_U + c];
            b_l[na][0] = Bl[kq * BS_U + c];
            b_l[na][1] = Bl[(kq + 4) * BS_U + c];
        }
#pragma unroll
        for (int ma = 0; ma < 2; ma++)
#pragma unroll
            for (int na = 0; na < 4; na++) {
                mma_f16(acc[ma][na], a_h[ma], b_h[na]);
                mma_f16(acc[ma][na], a_l[ma], b_h[na]);
                mma_f16(acc[ma][na], a_h[ma], b_l[na]);
            }
    }

#pragma unroll
    for (int ma = 0; ma < 2; ma++) {
        int row = n0 + wm + ma * 16 + (lane >> 2);
#pragma unroll
        for (int na = 0; na < 4; na++) {
            int col = m0 + wn + na * 8 + (lane & 3) * 2;
            C[(size_t)row * ldc + col]           = acc[ma][na][0];
            C[(size_t)row * ldc + col + 1]       = acc[ma][na][1];
            C[(size_t)(row + 8) * ldc + col]     = acc[ma][na][2];
            C[(size_t)(row + 8) * ldc + col + 1] = acc[ma][na][3];
        }
    }
}

// ---------------- attention fp16x3 MMA: 64x64 tile, in-loop split ----------------
// MODE 0 (scores): A=Q slice (lda=EE), B=Kt[z] (ldb=S12), C=S[z] plain, K=HD
// MODE 1 (pv):     A=S[z] (lda=S12), B=V slice (ldb=EE), C=att NH-scatter, K=S12
#define ZAS 12
#define ZBS 72
template<int MODE>
__global__ __launch_bounds__(256, 3)
void k_att16(const float* __restrict__ A, const float* __restrict__ B,
             float* __restrict__ C) {
    __shared__ uint32_t sAh[64 * ZAS], sAl[64 * ZAS];
    __shared__ uint32_t sBh[8 * ZBS], sBl[8 * ZBS];
    int tid = threadIdx.x, warp = tid >> 5, lane = tid & 31;
    int z = blockIdx.z, b = z / NH, h = z - b * NH;
    int n0 = blockIdx.y * 64, m0 = blockIdx.x * 64;

    const float* Ap;
    const float* Bp;
    int lda, ldb, K;
    if (MODE == 0) {
        Ap = A + (size_t)b * S12 * EE + h * HD; lda = EE;
        Bp = B + (size_t)z * HD * S12;          ldb = S12;
        K = HD;
    } else {
        Ap = A + (size_t)z * S12 * S12;         lda = S12;
        Bp = B + (size_t)b * S12 * EE + h * HD; ldb = EE;
        K = S12;
    }

    int wm = (warp >> 2) * 32;      // 2 row-groups of 32
    int wn = (warp & 3) * 16;       // 4 col-groups of 16
    int ar = tid >> 2, ak4 = (tid & 3) * 4, ak2 = (tid & 3) * 2;
    int bk2 = tid >> 5, bm = (tid & 31) * 2;
    float acc[2][2][4] = {};

    for (int k0 = 0; k0 < K; k0 += 16) {
        __syncthreads();
        {
            float4 a = *(const float4*)&Ap[(size_t)(n0 + ar) * lda + k0 + ak4];
            float hx, lx, hy, ly, hz, lz, hw, lw;
            split_f16(a.x, hx, lx); split_f16(a.y, hy, ly);
            split_f16(a.z, hz, lz); split_f16(a.w, hw, lw);
            sAh[ar * ZAS + ak2]     = pack_h2(hx, hy);
            sAh[ar * ZAS + ak2 + 1] = pack_h2(hz, hw);
            sAl[ar * ZAS + ak2]     = pack_h2(lx, ly);
            sAl[ar * ZAS + ak2 + 1] = pack_h2(lz, lw);
            float2 b0 = *(const float2*)&Bp[(size_t)(k0 + 2 * bk2) * ldb + m0 + bm];
            float2 b1 = *(const float2*)&Bp[(size_t)(k0 + 2 * bk2 + 1) * ldb + m0 + bm];
            float h0, l0, h1, l1;
            split_f16(b0.x, h0, l0); split_f16(b1.x, h1, l1);
            sBh[bk2 * ZBS + bm]     = pack_h2(h0, h1);
            sBl[bk2 * ZBS + bm]     = pack_h2(l0, l1);
            split_f16(b0.y, h0, l0); split_f16(b1.y, h1, l1);
            sBh[bk2 * ZBS + bm + 1] = pack_h2(h0, h1);
            sBl[bk2 * ZBS + bm + 1] = pack_h2(l0, l1);
        }
        __syncthreads();

        uint32_t a_h[2][4], a_l[2][4];
        int r0 = wm + (lane >> 2);
        int kq = lane & 3;
#pragma unroll
        for (int ma = 0; ma < 2; ma++) {
            int r = r0 + ma * 16;
            a_h[ma][0] = sAh[r * ZAS + kq];
            a_h[ma][1] = sAh[(r + 8) * ZAS + kq];
            a_h[ma][2] = sAh[r * ZAS + kq + 4];
            a_h[ma][3] = sAh[(r + 8) * ZAS + kq + 4];
            a_l[ma][0] = sAl[r * ZAS + kq];
            a_l[ma][1] = sAl[(r + 8) * ZAS + kq];
            a_l[ma][2] = sAl[r * ZAS + kq + 4];
            a_l[ma][3] = sAl[(r + 8) * ZAS + kq + 4];
        }
        uint32_t b_h[2][2], b_l[2][2];
#pragma unroll
        for (int na = 0; na < 2; na++) {
            int c = wn + na * 8 + (lane >> 2);
            b_h[na][0] = sBh[kq * ZBS + c];
            b_h[na][1] = sBh[(kq + 4) * ZBS + c];
            b_l[na][0] = sBl[kq * ZBS + c];
            b_l[na][1] = sBl[(kq + 4) * ZBS + c];
        }
#pragma unroll
        for (int ma = 0; ma < 2; ma++)
#pragma unroll
            for (int na = 0; na < 2; na++) {
                mma_f16(acc[ma][na], a_h[ma], b_h[na]);
                mma_f16(acc[ma][na], a_l[ma], b_h[na]);
                mma_f16(acc[ma][na], a_h[ma], b_l[na]);
            }
    }

#pragma unroll
    for (int ma = 0; ma < 2; ma++) {
        int row = n0 + wm + ma * 16 + (lane >> 2);
#pragma unroll
        for (int na = 0; na < 2; na++) {
            int col = m0 + wn + na * 8 + (lane & 3) * 2;
            if (MODE == 0) {
                float* Cz = C + (size_t)z * S12 * S12;
                Cz[(size_t)row * S12 + col]           = acc[ma][na][0];
                Cz[(size_t)row * S12 + col + 1]       = acc[ma][na][1];
                Cz[(size_t)(row + 8) * S12 + col]     = acc[ma][na][2];
                Cz[(size_t)(row + 8) * S12 + col + 1] = acc[ma][na][3];
            } else {
                float* o0 = C + (size_t)(b * S12 + row) * EE + h;
                float* o1 = C + (size_t)(b * S12 + row + 8) * EE + h;
                o0[col * NH]       = acc[ma][na][0];
                o0[(col + 1) * NH] = acc[ma][na][1];
                o1[col * NH]       = acc[ma][na][2];
                o1[(col + 1) * NH] = acc[ma][na][3];
            }
        }
    }
}

// ---------------- per-head K transpose (fp32, coalesced) ----------------
__global__ void k_transKf(const float* __restrict__ Kf, float* __restrict__ Kt) {
    __shared__ float sm[32][33];
    int z = blockIdx.z, b = z / NH, h = z - b * NH;
    int j0 = blockIdx.x * 32, d0 = blockIdx.y * 32;
    int tx = threadIdx.x, ty = threadIdx.y;   // 32 x 8
    const float* kb = Kf + (size_t)b * S12 * EE + h * HD;
#pragma unroll
    for (int jy = 0; jy < 4; jy++) {
        int j = ty * 4 + jy;
        sm[j][tx] = kb[(size_t)(j0 + j) * EE + d0 + tx];
    }
    __syncthreads();
    float* ktz = Kt + (size_t)z * HD * S12;
#pragma unroll
    for (int dy = 0; dy < 4; dy++) {
        int d = ty * 4 + dy;
        ktz[(size_t)(d0 + d) * S12 + j0 + tx] = sm[tx][d];
    }
}

// ---------------- LN over 768 (+RoPE) fp32 in-place ----------------
__global__ void k_ln768(float* __restrict__ X, const float* __restrict__ w,
                        const float* __restrict__ bb, int doRope) {
    __shared__ float s[768];
    __shared__ float sh[32];
    int n = blockIdx.x, tid = threadIdx.x;
    float* row = X + (size_t)n * 768;
    float partial = 0.f;
#pragma unroll
    for (int it = 0; it < 3; it++) { int j = tid + it * 256; float v = row[j]; s[j] = v; partial += v; }
    float u = blk_sum(partial, sh) * (1.f / 768.f);
    float p2 = 0.f;
#pragma unroll
    for (int it = 0; it < 3; it++) { int j = tid + it * 256; float dd = s[j] - u; p2 += dd * dd; }
    float var = blk_sum(p2, sh) * (1.f / 768.f);
    float rinv = rsqrtf(var + 1e-6f);
#pragma unroll
    for (int it = 0; it < 3; it++) { int j = tid + it * 256; s[j] = (s[j] - u) * rinv * w[j] + bb[j]; }
    __syncthreads();
    if (doRope) {
        int l = n % S12;
#pragma unroll
        for (int it = 0; it < 3; it++) {
            int j = tid + it * 256;
            int jm = (j < 384) ? j : j - 384;
            float inv = exp2f(-(float)jm * (13.287712379549449f / 384.f));
            float f = (float)l * inv;
            float cs, sn;
            rope_trig(f, cs, sn);
            float rot = (j < 384) ? -s[j + 384] : s[j - 384];
            row[j] = s[j] * cs + rot * sn;
        }
    } else {
#pragma unroll
        for (int it = 0; it < 3; it++) { int j = tid + it * 256; row[j] = s[j]; }
    }
}

// ---------------- rowwise softmax with scale 1/8 (in place, fp32) ----------------
__global__ void k_softmax(float* __restrict__ S) {
    __shared__ float sh[32];
    int row = blockIdx.x;
    float* r = S + (size_t)row * S12;
    int tid = threadIdx.x;
    float vals[7];
    float mx = -3.4e38f;
    for (int i = 0, j = tid; j < S12; j += 256, i++) { float v = r[j]; vals[i] = v; mx = fmaxf(mx, v); }
    mx = blk_max(mx, sh);
    float sum = 0.f;
    for (int i = 0, j = tid; j < S12; j += 256, i++) {
        float e = expf((vals[i] - mx) * 0.125f);
        vals[i] = e; sum += e;
    }
    sum = blk_sum(sum, sh);
    float inv = 1.f / sum;
    for (int i = 0, j = tid; j < S12; j += 256, i++) r[j] = vals[i] * inv;
}

// ---------------- weight transposes ----------------
__global__ void k_transW1(const float* __restrict__ in, float* __restrict__ out) {
    int idx = blockIdx.x * blockDim.x + threadIdx.x;
    if (idx >= 192 * 48) return;
    int t = idx / 48, j = idx - t * 48;
    out[j * 192 + t] = in[idx];
}
__global__ void k_transW2(const float* __restrict__ in, float* __restrict__ out) {
    int idx = blockIdx.x * blockDim.x + threadIdx.x;
    if (idx >= EE * KK2) return;
    int o = idx / KK2, rest = idx - o * KK2;
    int t = rest >> 3, par = rest & 7;
    out[(size_t)(par * 192 + t) * EE + o] = in[idx];
}
__global__ void k_transWd(const float* __restrict__ in, float* __restrict__ out) {
    int idx = blockIdx.x * blockDim.x + threadIdx.x;
    if (idx >= EE * KK2) return;
    int i = idx / KK2, rest = idx - i * KK2;
    int o = rest >> 3, r = rest & 7;
    out[(size_t)i * KK2 + r * 192 + o] = in[idx];
}

// ---------------- LN192+GELU fp32 in place ----------------
__global__ void k_ln192gelu(float* __restrict__ X, const float* __restrict__ g,
                            const float* __restrict__ bb) {
    __shared__ float sh[32];
    int n = blockIdx.x, t = threadIdx.x;
    float* row = X + (size_t)n * 192;
    float v = row[t];
    float u = blk_sum(v, sh) * (1.f / 192.f);
    float dd = v - u;
    float var = blk_sum(dd * dd, sh) * (1.f / 192.f);
    float xn = dd * rsqrtf(var + 1e-6f) * g[t] + bb[t];
    row[t] = xn * normcdff(xn);
}

// ---------------- final convT2s2 (192->6) + bias + residual ----------------
__global__ void k_debed2(const float* __restrict__ glo, const float* __restrict__ W,
                         const float* __restrict__ bias, const float* __restrict__ res,
                         float* __restrict__ out) {
    __shared__ float row[192];
    int bid = blockIdx.x;
    int bn = bid / S24, pos = bid - bn * S24;
    int H = pos / 576, Wp = (pos / 24) % 24, D = pos % 24;
    int n1 = (H >> 1) * 144 + (Wp >> 1) * 12 + (D >> 1);
    int rr = (H & 1) * 4 + (Wp & 1) * 2 + (D & 1);
    const float* rp = glo + (size_t)(bn * S12 + n1) * KK2 + rr * 192;
    int t = threadIdx.x;
    for (int j = t; j < 192; j += 64) row[j] = rp[j];
    __syncthreads();
    if (t < 48) {
        int c = t >> 3, r2 = t & 7;
        float acc = 0.f;
#pragma unroll
        for (int o = 0; o < 192; o++) acc += row[o] * __ldg(&W[o * 48 + c * 8 + r2]);
        int Hf = 2 * H + (r2 >> 2), Wf = 2 * Wp + ((r2 >> 1) & 1), Df = 2 * D + (r2 & 1);
        size_t oi = (((size_t)(bn * 6 + c) * 48 + Hf) * 48 + Wf) * 48 + Df;
        out[oi] = acc + bias[c] + res[oi];
    }
}

// ---------------- launch ----------------
extern "C" void kernel_launch(void* const* d_in, const int* in_sizes, int n_in,
                              void* d_out, int out_size) {
    const float* x     = (const float*)d_in[0];
    const float* skip  = (const float*)d_in[1];
    const float* o_tw1 = (const float*)d_in[20];
    const float* o_g   = (const float*)d_in[21];
    const float* o_b   = (const float*)d_in[22];
    const float* o_tw2 = (const float*)d_in[23];
    const float* o_tb2 = (const float*)d_in[24];
    const float* ns_w  = (const float*)d_in[25];
    const float* ns_b  = (const float*)d_in[26];
    const float* nx_w  = (const float*)d_in[27];
    const float* nx_b  = (const float*)d_in[28];
    const float* no_w  = (const float*)d_in[29];
    const float* no_b  = (const float*)d_in[30];
    float* out = (float*)d_out;

    float *patchs, *patchx, *h1b, *q, *k, *v, *Wt, *S, *att, *deb, *Kt;
    cudaGetSymbolAddress((void**)&patchs, g_patchs);
    cudaGetSymbolAddress((void**)&patchx, g_patchx);
    cudaGetSymbolAddress((void**)&h1b,    g_h1b);
    cudaGetSymbolAddress((void**)&q,      g_q);
    cudaGetSymbolAddress((void**)&k,      g_k);
    cudaGetSymbolAddress((void**)&v,      g_v);
    cudaGetSymbolAddress((void**)&Wt,     g_Wt);
    cudaGetSymbolAddress((void**)&S,      g_S);
    cudaGetSymbolAddress((void**)&att,    g_att);
    cudaGetSymbolAddress((void**)&deb,    g_deb);
    cudaGetSymbolAddress((void**)&Kt,     g_Kt);

    k_patch<<<(NPATCH * 8 + 255) / 256, 256>>>(skip, ns_w, ns_b, patchs);
    k_patch<<<(NPATCH * 8 + 255) / 256, 256>>>(x,    nx_w, nx_b, patchx);

    const float* stem_patch[3] = {patchs, patchx, patchx};
    float* stem_out[3] = {q, k, v};
    int rope[3] = {1, 1, 0};
    for (int si = 0; si < 3; si++) {
        int base = 2 + si * 6;
        const float* w1 = (const float*)d_in[base + 0];
        const float* g1 = (const float*)d_in[base + 1];
        const float* b1 = (const float*)d_in[base + 2];
        const float* w2 = (const float*)d_in[base + 3];
        const float* g2 = (const float*)d_in[base + 4];
        const float* b2 = (const float*)d_in[base + 5];
        k_transW1<<<(192 * 48 + 255) / 256, 256>>>(w1, Wt);
        dim3 g1g(192 / 64, NPATCH / 64);
        k_gemm64<<<g1g, 256>>>(stem_patch[si], Wt, h1b, 48, 48, 192, 192);
        k_ln192gelu<<<NPATCH, 192>>>(h1b, g1, b1);
        k_transW2<<<(EE * KK2 + 255) / 256, 256>>>(w2, Wt);
        dim3 gg(EE / 128, NTOK / 64);
        k_mma_fp16<<<gg, 256>>>(h1b, Wt, stem_out[si], KK2, KK2, EE, EE);
        k_ln768<<<NTOK, 256>>>(stem_out[si], g2, b2, rope[si]);
    }

    // attention: fp16x3 MMA scores + fp32 softmax + fp16x3 MMA PV
    k_transKf<<<dim3(S12 / 32, 2, B2 * NH), dim3(32, 8)>>>(k, Kt);
    k_att16<0><<<dim3(27, 27, 24), 256>>>(q, Kt, S);
    k_softmax<<<B2 * NH * S12, 256>>>(S);
    k_att16<1><<<dim3(1, 27, 24), 256>>>(S, v, att);

    k_ln768<<<NTOK, 256>>>(att, no_w, no_b, 0);
    k_transWd<<<(EE * KK2 + 255) / 256, 256>>>(o_tw1, Wt);
    dim3 gd(KK2 / 128, NTOK / 64);
    k_mma_fp16<<<gd, 256>>>(att, Wt, deb, EE, EE, KK2, KK2);
    k_ln192gelu<<<NTOK * 8, 192>>>(deb, o_g, o_b);
    k_debed2<<<B2 * S24, 64>>>(deb, o_tw2, o_tb2, skip, out);
}

// round 17
// speedup vs baseline: 1.4839x; 1.0793x over previous
#include <cuda_runtime.h>
#include <cuda_fp16.h>
#include <math.h>
#include <stdint.h>

// ---------------- problem dims ----------------
#define B2   2
#define S48  110592
#define S24  13824
#define S12  1728
#define EE   768
#define NH   12
#define HD   64
#define NTOK (B2*S12)     // 3456
#define KK2  1536
#define NPATCH (B2*S24)   // 27648
#define KPAIRS 864        // S12/2

// ---------------- scratch ----------------
__device__ float g_patchs[NPATCH*48];
__device__ float g_patchx[NPATCH*48];
__device__ float g_h1b   [NPATCH*192];
__device__ float g_q     [NTOK*EE];
__device__ float g_k     [NTOK*EE];
__device__ float g_v     [NTOK*EE];
__device__ float g_Wt1   [48*192];
__device__ float g_S     [(size_t)B2*NH*S12*S12];
__device__ float g_att   [NTOK*EE];
__device__ float g_deb   [NTOK*KK2];
// packed vertical-pair (half2 as uint32) B operands
__device__ uint32_t g_w2ph[768*768];      // conv2 W: [768 kpairs][768]
__device__ uint32_t g_w2pl[768*768];
__device__ uint32_t g_wdph[384*1536];     // debed W: [384 kpairs][1536]
__device__ uint32_t g_wdpl[384*1536];
__device__ uint32_t g_ktph[24*32*S12];    // K^T packed: [(z,dpair)][j]
__device__ uint32_t g_ktpl[24*32*S12];
__device__ uint32_t g_vph [B2*KPAIRS*EE]; // V packed: [b][kpair][c]
__device__ uint32_t g_vpl [B2*KPAIRS*EE];

// ---------------- helpers ----------------
__device__ __forceinline__ float blk_sum(float v, float* sh) {
    int lane = threadIdx.x & 31;
#pragma unroll
    for (int o = 16; o; o >>= 1) v += __shfl_xor_sync(0xffffffffu, v, o);
    __syncthreads();
    if (lane == 0) sh[threadIdx.x >> 5] = v;
    __syncthreads();
    int nw = blockDim.x >> 5;
    v = (lane < nw) ? sh[lane] : 0.f;
#pragma unroll
    for (int o = 16; o; o >>= 1) v += __shfl_xor_sync(0xffffffffu, v, o);
    return v;
}
__device__ __forceinline__ float blk_max(float v, float* sh) {
    int lane = threadIdx.x & 31;
#pragma unroll
    for (int o = 16; o; o >>= 1) v = fmaxf(v, __shfl_xor_sync(0xffffffffu, v, o));
    __syncthreads();
    if (lane == 0) sh[threadIdx.x >> 5] = v;
    __syncthreads();
    int nw = blockDim.x >> 5;
    v = (lane < nw) ? sh[lane] : -3.4e38f;
#pragma unroll
    for (int o = 16; o; o >>= 1) v = fmaxf(v, __shfl_xor_sync(0xffffffffu, v, o));
    return v;
}
__device__ __forceinline__ void rope_trig(float f, float& cs, float& sn) {
    float n = rintf(f * 0.15915494309189535f);
    float r = fmaf(-n, 6.28125f, f);
    r = fmaf(-n, 1.9353071795864769e-3f, r);
    cs = cosf(r);
    sn = sinf(r);
}
__device__ __forceinline__ uint32_t pack_h2(float a, float b) {
    __half2 h = __halves2half2(__float2half_rn(a), __float2half_rn(b));
    return *(uint32_t*)&h;
}
__device__ __forceinline__ void split_f16(float x, float& hi, float& lo) {
    __half h = __float2half_rn(x);
    hi = __half2float(h);
    lo = x - hi;
}
__device__ __forceinline__ void hsplit(float x, __half& h, __half& l) {
    h = __float2half_rn(x);
    l = __float2half_rn(x - __half2float(h));
}
__device__ __forceinline__ uint32_t h2u(__half a, __half b) {
    __half2 t = __halves2half2(a, b);
    return *(uint32_t*)&t;
}
__device__ __forceinline__ void mma_f16(float* c, const uint32_t* a, const uint32_t* b) {
    asm volatile(
        "mma.sync.aligned.m16n8k16.row.col.f32.f16.f16.f32 "
        "{%0,%1,%2,%3}, {%4,%5,%6,%7}, {%8,%9}, {%0,%1,%2,%3};\n"
        : "+f"(c[0]), "+f"(c[1]), "+f"(c[2]), "+f"(c[3])
        : "r"(a[0]), "r"(a[1]), "r"(a[2]), "r"(a[3]), "r"(b[0]), "r"(b[1]));
}

// ---------------- fused LN6 + patch gather ----------------
__global__ void k_patch(const float* __restrict__ in, const float* __restrict__ w,
                        const float* __restrict__ bb, float* __restrict__ out) {
    int id = blockIdx.x * blockDim.x + threadIdx.x;
    if (id >= NPATCH * 8) return;
    int kpq = id & 7;
    int p = id >> 3;
    int bn = p / S24, pos = p - bn * S24;
    int h = pos / 576, w24 = (pos / 24) % 24, d = pos % 24;
    int k = kpq >> 2, pp = (kpq >> 1) & 1, qq = kpq & 1;
    size_t sp = ((size_t)(2 * h + k) * 48 + 2 * w24 + pp) * 48 + 2 * d + qq;
    const float* base = in + (size_t)bn * 6 * S48 + sp;
    float v[6], u = 0.f;
#pragma unroll
    for (int c = 0; c < 6; c++) { v[c] = base[(size_t)c * S48]; u += v[c]; }
    u *= (1.f / 6.f);
    float s = 0.f;
#pragma unroll
    for (int c = 0; c < 6; c++) { float dd = v[c] - u; s += dd * dd; }
    s *= (1.f / 6.f);
    float r = rsqrtf(s + 1e-6f);
    int token = bn * S12 + (h >> 1) * 144 + (w24 >> 1) * 12 + (d >> 1);
    int par = (h & 1) * 4 + (w24 & 1) * 2 + (d & 1);
    float* ob = out + ((size_t)token * 8 + par) * 48 + kpq;
#pragma unroll
    for (int c = 0; c < 6; c++) ob[c * 8] = (v[c] - u) * r * w[c] + bb[c];
}

// ---------------- small SGEMM (conv1): 64x64 ----------------
__global__ void k_gemm64(const float* __restrict__ A, const float* __restrict__ B,
                         float* __restrict__ C, int K, int lda, int ldb, int ldc) {
    __shared__ float As[16][64];
    __shared__ float Bs[16][64];
    int tid = threadIdx.x;
    int tx = tid & 15, ty = tid >> 4;
    int n0 = blockIdx.y * 64, m0 = blockIdx.x * 64;
    int lr = tid >> 2, lc = (tid & 3) * 4;
    int br = tid >> 4, bc = (tid & 15) * 4;
    const float* Ap = A + (size_t)(n0 + lr) * lda + lc;
    const float* Bp = B + (size_t)br * ldb + m0 + bc;
    float acc[4][4] = {};
    for (int k0 = 0; k0 < K; k0 += 16) {
        float4 a  = *(const float4*)(Ap + k0);
        float4 bv = *(const float4*)(Bp + (size_t)k0 * ldb);
        __syncthreads();
        As[lc + 0][lr] = a.x; As[lc + 1][lr] = a.y; As[lc + 2][lr] = a.z; As[lc + 3][lr] = a.w;
        *(float4*)&Bs[br][bc] = bv;
        __syncthreads();
#pragma unroll
        for (int kk = 0; kk < 16; kk++) {
            float4 av = *(const float4*)&As[kk][ty * 4];
            float4 bw = *(const float4*)&Bs[kk][tx * 4];
            float aa[4] = {av.x, av.y, av.z, av.w};
            float bbv[4] = {bw.x, bw.y, bw.z, bw.w};
#pragma unroll
            for (int i = 0; i < 4; i++)
#pragma unroll
                for (int j = 0; j < 4; j++) acc[i][j] += aa[i] * bbv[j];
        }
    }
#pragma unroll
    for (int i = 0; i < 4; i++) {
        float4 o = make_float4(acc[i][0], acc[i][1], acc[i][2], acc[i][3]);
        *(float4*)&C[(size_t)(n0 + ty * 4 + i) * ldc + m0 + tx * 4] = o;
    }
}

// ---------------- dense fp16x3 MMA GEMM: A fp32 in-loop split, B pre-packed ----
// tile 64x128, k-step 16, 256 threads.
#define AS_U 12
#define BS_U 136
__global__ __launch_bounds__(256, 2)
void k_mma_fp16(const float* __restrict__ A,
                const uint32_t* __restrict__ Bph, const uint32_t* __restrict__ Bpl,
                float* __restrict__ C, int K, int lda, int ldb, int ldc) {
    __shared__ uint32_t Ah[64 * AS_U], Al[64 * AS_U];
    __shared__ uint32_t Bh[8 * BS_U], Bl[8 * BS_U];
    int tid = threadIdx.x;
    int warp = tid >> 5, lane = tid & 31;
    int n0 = blockIdx.y * 64;
    int m0 = blockIdx.x * 128;
    int wm = (warp >> 2) * 32;
    int wn = (warp & 3) * 32;
    int ar = tid >> 2, ak4 = (tid & 3) * 4, ak2 = (tid & 3) * 2;
    int bk2 = tid >> 5, bm = (tid & 31) * 4;
    float acc[2][4][4] = {};

    for (int k0 = 0; k0 < K; k0 += 16) {
        __syncthreads();
        {
            float4 a = *(const float4*)&A[(size_t)(n0 + ar) * lda + k0 + ak4];
            float hx, lx, hy, ly, hz, lz, hw, lw;
            split_f16(a.x, hx, lx); split_f16(a.y, hy, ly);
            split_f16(a.z, hz, lz); split_f16(a.w, hw, lw);
            Ah[ar * AS_U + ak2]     = pack_h2(hx, hy);
            Ah[ar * AS_U + ak2 + 1] = pack_h2(hz, hw);
            Al[ar * AS_U + ak2]     = pack_h2(lx, ly);
            Al[ar * AS_U + ak2 + 1] = pack_h2(lz, lw);
            size_t boff = (size_t)(k0 / 2 + bk2) * ldb + m0 + bm;
            *(uint4*)&Bh[bk2 * BS_U + bm] = *(const uint4*)&Bph[boff];
            *(uint4*)&Bl[bk2 * BS_U + bm] = *(const uint4*)&Bpl[boff];
        }
        __syncthreads();

        uint32_t a_h[2][4], a_l[2][4];
        int r0 = wm + (lane >> 2);
        int kq = lane & 3;
#pragma unroll
        for (int ma = 0; ma < 2; ma++) {
            int r = r0 + ma * 16;
            a_h[ma][0] = Ah[r * AS_U + kq];
            a_h[ma][1] = Ah[(r + 8) * AS_U + kq];
            a_h[ma][2] = Ah[r * AS_U + kq + 4];
            a_h[ma][3] = Ah[(r + 8) * AS_U + kq + 4];
            a_l[ma][0] = Al[r * AS_U + kq];
            a_l[ma][1] = Al[(r + 8) * AS_U + kq];
            a_l[ma][2] = Al[r * AS_U + kq + 4];
            a_l[ma][3] = Al[(r + 8) * AS_U + kq + 4];
        }
        uint32_t b_h[4][2], b_l[4][2];
#pragma unroll
        for (int na = 0; na < 4; na++) {
            int c = wn + na * 8 + (lane >> 2);
            b_h[na][0] = Bh[kq * BS_U + c];
            b_h[na][1] = Bh[(kq + 4) * BS_U + c];
            b_l[na][0] = Bl[kq * BS_U + c];
            b_l[na][1] = Bl[(kq + 4) * BS_U + c];
        }
#pragma unroll
        for (int ma = 0; ma < 2; ma++)
#pragma unroll
            for (int na = 0; na < 4; na++) {
                mma_f16(acc[ma][na], a_h[ma], b_h[na]);
                mma_f16(acc[ma][na], a_l[ma], b_h[na]);
                mma_f16(acc[ma][na], a_h[ma], b_l[na]);
            }
    }

#pragma unroll
    for (int ma = 0; ma < 2; ma++) {
        int row = n0 + wm + ma * 16 + (lane >> 2);
#pragma unroll
        for (int na = 0; na < 4; na++) {
            int col = m0 + wn + na * 8 + (lane & 3) * 2;
            C[(size_t)row * ldc + col]           = acc[ma][na][0];
            C[(size_t)row * ldc + col + 1]       = acc[ma][na][1];
            C[(size_t)(row + 8) * ldc + col]     = acc[ma][na][2];
            C[(size_t)(row + 8) * ldc + col + 1] = acc[ma][na][3];
        }
    }
}

// ---------------- attention fp16x3 MMA: A in-loop split, B pre-packed ----------------
// MODE 0 (scores): A=Q slice (lda=EE), B=Ktp[z] (ldb=S12 u32), C=S[z], K=HD
// MODE 1 (pv):     A=S[z] (lda=S12), B=Vp slice (ldb=EE u32), C=att NH-scatter, K=S12
#define ZAS 12
#define ZBS 72
template<int MODE>
__global__ __launch_bounds__(256, 3)
void k_att16(const float* __restrict__ A,
             const uint32_t* __restrict__ Bph, const uint32_t* __restrict__ Bpl,
             float* __restrict__ C) {
    __shared__ uint32_t sAh[64 * ZAS], sAl[64 * ZAS];
    __shared__ uint32_t sBh[8 * ZBS], sBl[8 * ZBS];
    int tid = threadIdx.x, warp = tid >> 5, lane = tid & 31;
    int z = blockIdx.z, b = z / NH, h = z - b * NH;
    int n0 = blockIdx.y * 64, m0 = blockIdx.x * 64;

    const float* Ap;
    const uint32_t* Bh_g;
    const uint32_t* Bl_g;
    int lda, ldb, K;
    if (MODE == 0) {
        Ap = A + (size_t)b * S12 * EE + h * HD;  lda = EE;
        Bh_g = Bph + (size_t)z * 32 * S12;       ldb = S12;
        Bl_g = Bpl + (size_t)z * 32 * S12;
        K = HD;
    } else {
        Ap = A + (size_t)z * S12 * S12;          lda = S12;
        Bh_g = Bph + (size_t)b * KPAIRS * EE + h * HD;  ldb = EE;
        Bl_g = Bpl + (size_t)b * KPAIRS * EE + h * HD;
        K = S12;
    }

    int wm = (warp >> 2) * 32;
    int wn = (warp & 3) * 16;
    int ar = tid >> 2, ak4 = (tid & 3) * 4, ak2 = (tid & 3) * 2;
    int bk2 = tid >> 5, bm = (tid & 31) * 2;
    float acc[2][2][4] = {};

    for (int k0 = 0; k0 < K; k0 += 16) {
        __syncthreads();
        {
            float4 a = *(const float4*)&Ap[(size_t)(n0 + ar) * lda + k0 + ak4];
            float hx, lx, hy, ly, hz, lz, hw, lw;
            split_f16(a.x, hx, lx); split_f16(a.y, hy, ly);
            split_f16(a.z, hz, lz); split_f16(a.w, hw, lw);
            sAh[ar * ZAS + ak2]     = pack_h2(hx, hy);
            sAh[ar * ZAS + ak2 + 1] = pack_h2(hz, hw);
            sAl[ar * ZAS + ak2]     = pack_h2(lx, ly);
            sAl[ar * ZAS + ak2 + 1] = pack_h2(lz, lw);
            size_t boff = (size_t)(k0 / 2 + bk2) * ldb + m0 + bm;
            *(uint2*)&sBh[bk2 * ZBS + bm] = *(const uint2*)&Bh_g[boff];
            *(uint2*)&sBl[bk2 * ZBS + bm] = *(const uint2*)&Bl_g[boff];
        }
        __syncthreads();

        uint32_t a_h[2][4], a_l[2][4];
        int r0 = wm + (lane >> 2);
        int kq = lane & 3;
#pragma unroll
        for (int ma = 0; ma < 2; ma++) {
            int r = r0 + ma * 16;
            a_h[ma][0] = sAh[r * ZAS + kq];
            a_h[ma][1] = sAh[(r + 8) * ZAS + kq];
            a_h[ma][2] = sAh[r * ZAS + kq + 4];
            a_h[ma][3] = sAh[(r + 8) * ZAS + kq + 4];
            a_l[ma][0] = sAl[r * ZAS + kq];
            a_l[ma][1] = sAl[(r + 8) * ZAS + kq];
            a_l[ma][2] = sAl[r * ZAS + kq + 4];
            a_l[ma][3] = sAl[(r + 8) * ZAS + kq + 4];
        }
        uint32_t b_h[2][2], b_l[2][2];
#pragma unroll
        for (int na = 0; na < 2; na++) {
            int c = wn + na * 8 + (lane >> 2);
            b_h[na][0] = sBh[kq * ZBS + c];
            b_h[na][1] = sBh[(kq + 4) * ZBS + c];
            b_l[na][0] = sBl[kq * ZBS + c];
            b_l[na][1] = sBl[(kq + 4) * ZBS + c];
        }
#pragma unroll
        for (int ma = 0; ma < 2; ma++)
#pragma unroll
            for (int na = 0; na < 2; na++) {
                mma_f16(acc[ma][na], a_h[ma], b_h[na]);
                mma_f16(acc[ma][na], a_l[ma], b_h[na]);
                mma_f16(acc[ma][na], a_h[ma], b_l[na]);
            }
    }

#pragma unroll
    for (int ma = 0; ma < 2; ma++) {
        int row = n0 + wm + ma * 16 + (lane >> 2);
#pragma unroll
        for (int na = 0; na < 2; na++) {
            int col = m0 + wn + na * 8 + (lane & 3) * 2;
            if (MODE == 0) {
                float* Cz = C + (size_t)z * S12 * S12;
                Cz[(size_t)row * S12 + col]           = acc[ma][na][0];
                Cz[(size_t)row * S12 + col + 1]       = acc[ma][na][1];
                Cz[(size_t)(row + 8) * S12 + col]     = acc[ma][na][2];
                Cz[(size_t)(row + 8) * S12 + col + 1] = acc[ma][na][3];
            } else {
                float* o0 = C + (size_t)(b * S12 + row) * EE + h;
                float* o1 = C + (size_t)(b * S12 + row + 8) * EE + h;
                o0[col * NH]       = acc[ma][na][0];
                o0[(col + 1) * NH] = acc[ma][na][1];
                o1[col * NH]       = acc[ma][na][2];
                o1[(col + 1) * NH] = acc[ma][na][3];
            }
        }
    }
}

// ---------------- packing kernels (numerically proven in R14) ----------------
// w2 [768 o][192 t][8 par] -> packed [kpair = par*96+t/2][o]
__global__ void k_splitW2p(const float* __restrict__ in, uint32_t* __restrict__ bh,
                           uint32_t* __restrict__ bl) {
    int idx = blockIdx.x * blockDim.x + threadIdx.x;
    if (idx >= 768 * 96 * 8) return;
    int o = idx % 768;
    int rest = idx / 768;
    int par = rest & 7, t2 = rest >> 3;
    float a = in[o * 1536 + (2 * t2) * 8 + par];
    float c = in[o * 1536 + (2 * t2 + 1) * 8 + par];
    __half ah, al, ch, cl;
    hsplit(a, ah, al); hsplit(c, ch, cl);
    size_t oi = (size_t)(par * 96 + t2) * 768 + o;
    bh[oi] = h2u(ah, ch);
    bl[oi] = h2u(al, cl);
}
// o_tw1 [768 i][192 o2][8 r] -> packed [kpair = i/2][m = r*192+o2]
__global__ void k_splitWdp(const float* __restrict__ in, uint32_t* __restrict__ bh,
                           uint32_t* __restrict__ bl) {
    int idx = blockIdx.x * blockDim.x + threadIdx.x;
    if (idx >= 384 * 1536) return;
    int m = idx % 1536;
    int i2 = idx / 1536;
    int r = m / 192, o2 = m % 192;
    float a = in[(2 * i2) * 1536 + o2 * 8 + r];
    float c = in[(2 * i2 + 1) * 1536 + o2 * 8 + r];
    __half ah, al, ch, cl;
    hsplit(a, ah, al); hsplit(c, ch, cl);
    bh[idx] = h2u(ah, ch);
    bl[idx] = h2u(al, cl);
}
// K -> per-head transposed packed: Ktp[(z, dpair)][j]
__global__ void k_transKp(const float* __restrict__ Kf, uint32_t* __restrict__ oh,
                          uint32_t* __restrict__ ol) {
    __shared__ float sm[32][33];
    int z = blockIdx.z, b = z / NH, h = z - b * NH;
    int j0 = blockIdx.x * 32, d0 = blockIdx.y * 32;
    int tx = threadIdx.x, ty = threadIdx.y;
    const float* kb = Kf + (size_t)b * S12 * EE + h * HD;
#pragma unroll
    for (int jy = 0; jy < 4; jy++) {
        int j = ty * 4 + jy;
        sm[j][tx] = kb[(size_t)(j0 + j) * EE + d0 + tx];
    }
    __syncthreads();
    uint32_t* ohz = oh + (size_t)z * 32 * S12;
    uint32_t* olz = ol + (size_t)z * 32 * S12;
#pragma unroll
    for (int dy = 0; dy < 2; dy++) {
        int dp = ty * 2 + dy;
        float a = sm[tx][2 * dp], c = sm[tx][2 * dp + 1];
        __half ah, al, ch, cl;
        hsplit(a, ah, al); hsplit(c, ch, cl);
        size_t oi = (size_t)(d0 / 2 + dp) * S12 + j0 + tx;
        ohz[oi] = h2u(ah, ch);
        olz[oi] = h2u(al, cl);
    }
}
// V -> packed token pairs: Vp[b][kpair][c]
__global__ void k_packV(const float* __restrict__ V, uint32_t* __restrict__ oh,
                        uint32_t* __restrict__ ol) {
    int idx = blockIdx.x * blockDim.x + threadIdx.x;
    if (idx >= B2 * KPAIRS * EE) return;
    int c = idx % EE;
    int kp = (idx / EE) % KPAIRS;
    int b = idx / (EE * KPAIRS);
    float a = V[((size_t)b * S12 + 2 * kp) * EE + c];
    float d = V[((size_t)b * S12 + 2 * kp + 1) * EE + c];
    __half ah, al, dh, dl;
    hsplit(a, ah, al); hsplit(d, dh, dl);
    oh[idx] = h2u(ah, dh);
    ol[idx] = h2u(al, dl);
}

// ---------------- LN over 768 (+RoPE) fp32 in-place ----------------
__global__ void k_ln768(float* __restrict__ X, const float* __restrict__ w,
                        const float* __restrict__ bb, int doRope) {
    __shared__ float s[768];
    __shared__ float sh[32];
    int n = blockIdx.x, tid = threadIdx.x;
    float* row = X + (size_t)n * 768;
    float partial = 0.f;
#pragma unroll
    for (int it = 0; it < 3; it++) { int j = tid + it * 256; float v = row[j]; s[j] = v; partial += v; }
    float u = blk_sum(partial, sh) * (1.f / 768.f);
    float p2 = 0.f;
#pragma unroll
    for (int it = 0; it < 3; it++) { int j = tid + it * 256; float dd = s[j] - u; p2 += dd * dd; }
    float var = blk_sum(p2, sh) * (1.f / 768.f);
    float rinv = rsqrtf(var + 1e-6f);
#pragma unroll
    for (int it = 0; it < 3; it++) { int j = tid + it * 256; s[j] = (s[j] - u) * rinv * w[j] + bb[j]; }
    __syncthreads();
    if (doRope) {
        int l = n % S12;
#pragma unroll
        for (int it = 0; it < 3; it++) {
            int j = tid + it * 256;
            int jm = (j < 384) ? j : j - 384;
            float inv = exp2f(-(float)jm * (13.287712379549449f / 384.f));
            float f = (float)l * inv;
            float cs, sn;
            rope_trig(f, cs, sn);
            float rot = (j < 384) ? -s[j + 384] : s[j - 384];
            row[j] = s[j] * cs + rot * sn;
        }
    } else {
#pragma unroll
        for (int it = 0; it < 3; it++) { int j = tid + it * 256; row[j] = s[j]; }
    }
}

// ---------------- rowwise softmax with scale 1/8 (in place, fp32) ----------------
__global__ void k_softmax(float* __restrict__ S) {
    __shared__ float sh[32];
    int row = blockIdx.x;
    float* r = S + (size_t)row * S12;
    int tid = threadIdx.x;
    float vals[7];
    float mx = -3.4e38f;
    for (int i = 0, j = tid; j < S12; j += 256, i++) { float v = r[j]; vals[i] = v; mx = fmaxf(mx, v); }
    mx = blk_max(mx, sh);
    float sum = 0.f;
    for (int i = 0, j = tid; j < S12; j += 256, i++) {
        float e = expf((vals[i] - mx) * 0.125f);
        vals[i] = e; sum += e;
    }
    sum = blk_sum(sum, sh);
    float inv = 1.f / sum;
    for (int i = 0, j = tid; j < S12; j += 256, i++) r[j] = vals[i] * inv;
}

// ---------------- conv1 weight transpose ----------------
__global__ void k_transW1(const float* __restrict__ in, float* __restrict__ out) {
    int idx = blockIdx.x * blockDim.x + threadIdx.x;
    if (idx >= 192 * 48) return;
    int t = idx / 48, j = idx - t * 48;
    out[j * 192 + t] = in[idx];
}

// ---------------- LN192+GELU fp32 in place ----------------
__global__ void k_ln192gelu(float* __restrict__ X, const float* __restrict__ g,
                            const float* __restrict__ bb) {
    __shared__ float sh[32];
    int n = blockIdx.x, t = threadIdx.x;
    float* row = X + (size_t)n * 192;
    float v = row[t];
    float u = blk_sum(v, sh) * (1.f / 192.f);
    float dd = v - u;
    float var = blk_sum(dd * dd, sh) * (1.f / 192.f);
    float xn = dd * rsqrtf(var + 1e-6f) * g[t] + bb[t];
    row[t] = xn * normcdff(xn);
}

// ---------------- final convT2s2 (192->6) + bias + residual ----------------
__global__ void k_debed2(const float* __restrict__ glo, const float* __restrict__ W,
                         const float* __restrict__ bias, const float* __restrict__ res,
                         float* __restrict__ out) {
    __shared__ float row[192];
    int bid = blockIdx.x;
    int bn = bid / S24, pos = bid - bn * S24;
    int H = pos / 576, Wp = (pos / 24) % 24, D = pos % 24;
    int n1 = (H >> 1) * 144 + (Wp >> 1) * 12 + (D >> 1);
    int rr = (H & 1) * 4 + (Wp & 1) * 2 + (D & 1);
    const float* rp = glo + (size_t)(bn * S12 + n1) * KK2 + rr * 192;
    int t = threadIdx.x;
    for (int j = t; j < 192; j += 64) row[j] = rp[j];
    __syncthreads();
    if (t < 48) {
        int c = t >> 3, r2 = t & 7;
        float acc = 0.f;
#pragma unroll
        for (int o = 0; o < 192; o++) acc += row[o] * __ldg(&W[o * 48 + c * 8 + r2]);
        int Hf = 2 * H + (r2 >> 2), Wf = 2 * Wp + ((r2 >> 1) & 1), Df = 2 * D + (r2 & 1);
        size_t oi = (((size_t)(bn * 6 + c) * 48 + Hf) * 48 + Wf) * 48 + Df;
        out[oi] = acc + bias[c] + res[oi];
    }
}

// ---------------- launch ----------------
extern "C" void kernel_launch(void* const* d_in, const int* in_sizes, int n_in,
                              void* d_out, int out_size) {
    const float* x     = (const float*)d_in[0];
    const float* skip  = (const float*)d_in[1];
    const float* o_tw1 = (const float*)d_in[20];
    const float* o_g   = (const float*)d_in[21];
    const float* o_b   = (const float*)d_in[22];
    const float* o_tw2 = (const float*)d_in[23];
    const float* o_tb2 = (const float*)d_in[24];
    const float* ns_w  = (const float*)d_in[25];
    const float* ns_b  = (const float*)d_in[26];
    const float* nx_w  = (const float*)d_in[27];
    const float* nx_b  = (const float*)d_in[28];
    const float* no_w  = (const float*)d_in[29];
    const float* no_b  = (const float*)d_in[30];
    float* out = (float*)d_out;

    float *patchs, *patchx, *h1b, *q, *k, *v, *Wt1, *S, *att, *deb;
    uint32_t *w2ph, *w2pl, *wdph, *wdpl, *ktph, *ktpl, *vph, *vpl;
    cudaGetSymbolAddress((void**)&patchs, g_patchs);
    cudaGetSymbolAddress((void**)&patchx, g_patchx);
    cudaGetSymbolAddress((void**)&h1b,    g_h1b);
    cudaGetSymbolAddress((void**)&q,      g_q);
    cudaGetSymbolAddress((void**)&k,      g_k);
    cudaGetSymbolAddress((void**)&v,      g_v);
    cudaGetSymbolAddress((void**)&Wt1,    g_Wt1);
    cudaGetSymbolAddress((void**)&S,      g_S);
    cudaGetSymbolAddress((void**)&att,    g_att);
    cudaGetSymbolAddress((void**)&deb,    g_deb);
    cudaGetSymbolAddress((void**)&w2ph,   g_w2ph);
    cudaGetSymbolAddress((void**)&w2pl,   g_w2pl);
    cudaGetSymbolAddress((void**)&wdph,   g_wdph);
    cudaGetSymbolAddress((void**)&wdpl,   g_wdpl);
    cudaGetSymbolAddress((void**)&ktph,   g_ktph);
    cudaGetSymbolAddress((void**)&ktpl,   g_ktpl);
    cudaGetSymbolAddress((void**)&vph,    g_vph);
    cudaGetSymbolAddress((void**)&vpl,    g_vpl);

    k_patch<<<(NPATCH * 8 + 255) / 256, 256>>>(skip, ns_w, ns_b, patchs);
    k_patch<<<(NPATCH * 8 + 255) / 256, 256>>>(x,    nx_w, nx_b, patchx);

    const float* stem_patch[3] = {patchs, patchx, patchx};
    float* stem_out[3] = {q, k, v};
    int rope[3] = {1, 1, 0};
    for (int si = 0; si < 3; si++) {
        int base = 2 + si * 6;
        const float* w1 = (const float*)d_in[base + 0];
        const float* g1 = (const float*)d_in[base + 1];
        const float* b1 = (const float*)d_in[base + 2];
        const float* w2 = (const float*)d_in[base + 3];
        const float* g2 = (const float*)d_in[base + 4];
        const float* b2 = (const float*)d_in[base + 5];
        k_transW1<<<(192 * 48 + 255) / 256, 256>>>(w1, Wt1);
        dim3 g1g(192 / 64, NPATCH / 64);
        k_gemm64<<<g1g, 256>>>(stem_patch[si], Wt1, h1b, 48, 48, 192, 192);
        k_ln192gelu<<<NPATCH, 192>>>(h1b, g1, b1);
        k_splitW2p<<<(768 * 96 * 8 + 255) / 256, 256>>>(w2, w2ph, w2pl);
        dim3 gg(EE / 128, NTOK / 64);
        k_mma_fp16<<<gg, 256>>>(h1b, w2ph, w2pl, stem_out[si], KK2, KK2, EE, EE);
        k_ln768<<<NTOK, 256>>>(stem_out[si], g2, b2, rope[si]);
    }

    // attention: pack K^T and V, then fp16x3 MMA + fp32 softmax
    k_transKp<<<dim3(S12 / 32, 2, B2 * NH), dim3(32, 8)>>>(k, ktph, ktpl);
    k_packV<<<(B2 * KPAIRS * EE + 255) / 256, 256>>>(v, vph, vpl);
    k_att16<0><<<dim3(27, 27, 24), 256>>>(q, ktph, ktpl, S);
    k_softmax<<<B2 * NH * S12, 256>>>(S);
    k_att16<1><<<dim3(1, 27, 24), 256>>>(S, vph, vpl, att);

    k_ln768<<<NTOK, 256>>>(att, no_w, no_b, 0);
    k_splitWdp<<<(384 * 1536 + 255) / 256, 256>>>(o_tw1, wdph, wdpl);
    dim3 gd(KK2 / 128, NTOK / 64);
    k_mma_fp16<<<gd, 256>>>(att, wdph, wdpl, deb, EE, EE, KK2, KK2);
    k_ln192gelu<<<NTOK * 8, 192>>>(deb, o_g, o_b);
    k_debed2<<<B2 * S24, 64>>>(deb, o_tw2, o_tb2, skip, out);
}